// round 11
// baseline (speedup 1.0000x reference)
#include <cuda_runtime.h>
#include <cstdint>

// FM second-order term via split-TF32 mma.sync (m16n8k8), single kernel.
//   sum_emb = features @ W  (M=16384, K=200->208, N=64)
//   x = hi+lo (tf32 split); x@W ~ hi@Whi + hi@Wlo + lo@Whi, fp32 accum.
//   out[b] = sum_e sum_emb[b,e]^2 - sum_f features[b,f]^2 * w2sum[f]
// R11: prep fused back in (each CTA converts B itself, overlapped with the
// A cp.async flight) -> no second kernel, no inter-kernel serial cost.
// 512 thr = kg2 x mg4 x ng2 warps; warp tile m32 x n32 over its K-half
// (13 k8-steps), 8 independent accumulators, next-step frag prefetch.

typedef unsigned long long ull;

constexpr int F_DIM = 200;
constexpr int E_DIM = 64;
constexpr int MTILE = 128;
constexpr int THREADS = 512;
constexpr int NS = 26;               // k8-steps total (208 >= 200)

constexpr int SA_F = 212;            // A smem row stride (floats; 848B)
constexpr int SM_A    = 0;           // 128*848  = 108544
constexpr int SM_B    = 108544;      // 8*26*512 = 106496 (fragment-linear)
constexpr int SM_W2S  = 215040;      // 200*4
constexpr int SM_SQS  = 215840;      // 128*4
constexpr int SM_PART = 216352;      // 256*4
constexpr int SMEM_TOTAL = 217376;
constexpr int SM_CP   = 0;           // kg-partials alias A (33792 <= 108544)
constexpr int CP_S    = 66;          // partial-C row stride (floats)

__device__ __forceinline__ uint32_t smem_u32(const void* p) {
    return (uint32_t)__cvta_generic_to_shared(p);
}
__device__ __forceinline__ void cp_async16(uint32_t s, const void* g) {
    asm volatile("cp.async.cg.shared.global [%0], [%1], 16;" :: "r"(s), "l"(g));
}
__device__ __forceinline__ uint32_t cvt_tf32(float x) {
    uint32_t r; asm("cvt.rna.tf32.f32 %0, %1;" : "=r"(r) : "f"(x)); return r;
}
__device__ __forceinline__ float lds32f(uint32_t a) {
    float v; asm volatile("ld.shared.f32 %0, [%1];" : "=f"(v) : "r"(a)); return v;
}
__device__ __forceinline__ uint4 lds128(uint32_t a) {
    uint4 v;
    asm volatile("ld.shared.v4.b32 {%0,%1,%2,%3}, [%4];"
                 : "=r"(v.x), "=r"(v.y), "=r"(v.z), "=r"(v.w) : "r"(a));
    return v;
}
__device__ __forceinline__ void mma_tf32(float* c, uint32_t a0, uint32_t a1,
                                         uint32_t a2, uint32_t a3,
                                         uint32_t b0, uint32_t b1) {
    asm volatile(
        "mma.sync.aligned.m16n8k8.row.col.f32.tf32.tf32.f32 "
        "{%0,%1,%2,%3}, {%4,%5,%6,%7}, {%8,%9}, {%0,%1,%2,%3};"
        : "+f"(c[0]), "+f"(c[1]), "+f"(c[2]), "+f"(c[3])
        : "r"(a0), "r"(a1), "r"(a2), "r"(a3), "r"(b0), "r"(b1));
}

__global__ void __launch_bounds__(THREADS, 1)
fm_kernel(const float* __restrict__ features,
          const float* __restrict__ W,
          float* __restrict__ out)
{
    extern __shared__ __align__(16) char smem[];
    const uint32_t sb = smem_u32(smem);
    const int tid = threadIdx.x;
    const int w = tid >> 5, lane = tid & 31;
    const int kg = w >> 3;                 // K-half 0/1
    const int mg = (w >> 1) & 3;           // rows 32*mg..
    const int ng = w & 1;                  // cols 32*ng..
    const int gr = lane >> 2, gk = lane & 3;

    float* w2s   = (float*)(smem + SM_W2S);
    float* sqs   = (float*)(smem + SM_SQS);
    float* partF = (float*)(smem + SM_PART);
    float* cp    = (float*)(smem + SM_CP);

    const size_t rowbase = (size_t)blockIdx.x * MTILE;
    const float* fblk = features + rowbase * F_DIM;

    // ---- 1. cp.async A raw fp32: 128 rows x 50 chunks of 16B
    #pragma unroll
    for (int i = 0; i < 13; ++i) {
        const int p = tid + i * THREADS;
        if (p < 6400) {
            const int row = p / 50, ch = p - row * 50;
            cp_async16(sb + SM_A + row * 848 + ch * 16,
                       fblk + row * F_DIM + ch * 4);
        }
    }
    asm volatile("cp.async.commit_group;");

    // ---- 2. zero A K-pad cols [200,208)
    {
        const int row = tid >> 2, c0 = 200 + (tid & 3) * 2;
        *(float2*)(smem + SM_A + (row * SA_F + c0) * 4) = make_float2(0.f, 0.f);
    }

    // ---- 3. convert B in-CTA (overlaps A flight): 6656 fragment items
    // item i: bi = i>>5 (frag block, = t*26+s), l = i&31.
    // lane l holds {b0h,b1h,b0l,b1l}: b0=W[8s+l%4][8t+l/4], b1=W[8s+l%4+4][...]
    #pragma unroll
    for (int it = 0; it < 13; ++it) {
        const int i = tid + it * THREADS;
        const int bi = i >> 5, l = i & 31;
        const int t = bi / 26, s = bi - 26 * t;
        const int n = 8 * t + (l >> 2);
        const int k0 = 8 * s + (l & 3);
        const float b0 = (k0 < F_DIM) ? W[(size_t)k0 * E_DIM + n] : 0.f;
        const float b1 = (k0 + 4 < F_DIM) ? W[(size_t)(k0 + 4) * E_DIM + n] : 0.f;
        const uint32_t b0h = cvt_tf32(b0), b1h = cvt_tf32(b1);
        const uint32_t b0l = cvt_tf32(b0 - __uint_as_float(b0h));
        const uint32_t b1l = cvt_tf32(b1 - __uint_as_float(b1h));
        *(uint4*)(smem + SM_B + bi * 512 + l * 16) = make_uint4(b0h, b1h, b0l, b1l);
    }

    // ---- 4. w2sum[f] = sum_e W[f,e]^2 (L2-hot)
    if (tid < F_DIM) {
        const float4* wr = (const float4*)(W + (size_t)tid * E_DIM);
        float s = 0.f;
        #pragma unroll
        for (int i = 0; i < E_DIM / 4; ++i) {
            float4 v = wr[i];
            s = fmaf(v.x, v.x, s); s = fmaf(v.y, v.y, s);
            s = fmaf(v.z, v.z, s); s = fmaf(v.w, v.w, s);
        }
        w2s[tid] = s;
    }

    asm volatile("cp.async.wait_group 0;" ::: "memory");
    __syncthreads();

    // ---- 5. MMA mainloop: warp tile m32 x n32 over K-half (13 k8-steps)
    const uint32_t aB = sb + SM_A + (uint32_t)(((32 * mg + gr) * SA_F + gk) * 4);
    const uint32_t bB = sb + SM_B + (uint32_t)(lane * 16);
    const int s0 = 13 * kg, s1 = s0 + 13;

    float c[2][4][4];
    #pragma unroll
    for (int mi = 0; mi < 2; ++mi)
        #pragma unroll
        for (int j = 0; j < 4; ++j)
            #pragma unroll
            for (int q = 0; q < 4; ++q) c[mi][j][q] = 0.f;

    // fragment loaders
    float a_c[4][2];  uint4 B_c[4];
    float a_n[4][2];  uint4 B_n[4];
    #pragma unroll
    for (int u = 0; u < 4; ++u)
        #pragma unroll
        for (int v = 0; v < 2; ++v)
            a_c[u][v] = lds32f(aB + (uint32_t)(s0 * 32 + v * 16 + u * 8 * SA_F * 4));
    #pragma unroll
    for (int j = 0; j < 4; ++j)
        B_c[j] = lds128(bB + (uint32_t)(((4 * ng + j) * 26 + s0) * 512));

    #pragma unroll
    for (int s = s0; s < s1; ++s) {
        // prefetch next step's fragments
        const int sn = (s + 1 < s1) ? s + 1 : s0;
        #pragma unroll
        for (int u = 0; u < 4; ++u)
            #pragma unroll
            for (int v = 0; v < 2; ++v)
                a_n[u][v] = lds32f(aB + (uint32_t)(sn * 32 + v * 16 + u * 8 * SA_F * 4));
        #pragma unroll
        for (int j = 0; j < 4; ++j)
            B_n[j] = lds128(bB + (uint32_t)(((4 * ng + j) * 26 + sn) * 512));

        // split A into tf32 hi/lo
        uint32_t ah[4][2], al[4][2];
        #pragma unroll
        for (int u = 0; u < 4; ++u)
            #pragma unroll
            for (int v = 0; v < 2; ++v) {
                ah[u][v] = __float_as_uint(a_c[u][v]) & 0xFFFFE000u;
                al[u][v] = __float_as_uint(a_c[u][v] - __uint_as_float(ah[u][v]));
            }

        // hh (8 independent), hl (8), lh (8)
        #pragma unroll
        for (int mi = 0; mi < 2; ++mi)
            #pragma unroll
            for (int j = 0; j < 4; ++j)
                mma_tf32(c[mi][j], ah[2 * mi][0], ah[2 * mi + 1][0],
                         ah[2 * mi][1], ah[2 * mi + 1][1], B_c[j].x, B_c[j].y);
        #pragma unroll
        for (int mi = 0; mi < 2; ++mi)
            #pragma unroll
            for (int j = 0; j < 4; ++j)
                mma_tf32(c[mi][j], ah[2 * mi][0], ah[2 * mi + 1][0],
                         ah[2 * mi][1], ah[2 * mi + 1][1], B_c[j].z, B_c[j].w);
        #pragma unroll
        for (int mi = 0; mi < 2; ++mi)
            #pragma unroll
            for (int j = 0; j < 4; ++j)
                mma_tf32(c[mi][j], al[2 * mi][0], al[2 * mi + 1][0],
                         al[2 * mi][1], al[2 * mi + 1][1], B_c[j].x, B_c[j].y);

        #pragma unroll
        for (int u = 0; u < 4; ++u)
            #pragma unroll
            for (int v = 0; v < 2; ++v) a_c[u][v] = a_n[u][v];
        #pragma unroll
        for (int j = 0; j < 4; ++j) B_c[j] = B_n[j];
    }

    // ---- 6. sq term from smem A (raw fp32)
    {
        const int row = tid >> 2, q = tid & 3;
        const uint32_t aRow = sb + SM_A + (uint32_t)(row * 848);
        float p0 = 0.f, p1 = 0.f;
        #pragma unroll
        for (int j = 0; j < 50; j += 2) {
            const int f0 = q + 4 * j, f1 = q + 4 * (j + 1);
            const float x0 = lds32f(aRow + f0 * 4);
            const float x1 = lds32f(aRow + f1 * 4);
            p0 = fmaf(x0 * x0, w2s[f0], p0);
            p1 = fmaf(x1 * x1, w2s[f1], p1);
        }
        float sq = p0 + p1;
        sq += __shfl_xor_sync(0xffffffffu, sq, 1);
        sq += __shfl_xor_sync(0xffffffffu, sq, 2);
        if (q == 0) sqs[row] = sq;
    }
    __syncthreads();   // all A-smem reads done; cp aliases A region

    // ---- 7. kg1 stores raw C partials
    if (kg == 1) {
        #pragma unroll
        for (int mi = 0; mi < 2; ++mi)
            #pragma unroll
            for (int j = 0; j < 4; ++j) {
                const int R = 32 * mg + 16 * mi + gr;
                const int C = 32 * ng + 8 * j + 2 * gk;
                *(float2*)&cp[R * CP_S + C] = make_float2(c[mi][j][0], c[mi][j][1]);
                *(float2*)&cp[(R + 8) * CP_S + C] = make_float2(c[mi][j][2], c[mi][j][3]);
            }
    }
    __syncthreads();

    // ---- 8. kg0: add partials, square, row-reduce over its 32 cols
    if (kg == 0) {
        #pragma unroll
        for (int mi = 0; mi < 2; ++mi) {
            float s_lo = 0.f, s_hi = 0.f;
            #pragma unroll
            for (int j = 0; j < 4; ++j) {
                const int R = 32 * mg + 16 * mi + gr;
                const int C = 32 * ng + 8 * j + 2 * gk;
                float2 p0 = *(const float2*)&cp[R * CP_S + C];
                float2 p1 = *(const float2*)&cp[(R + 8) * CP_S + C];
                const float u0 = c[mi][j][0] + p0.x, u1 = c[mi][j][1] + p0.y;
                const float v0 = c[mi][j][2] + p1.x, v1 = c[mi][j][3] + p1.y;
                s_lo = fmaf(u0, u0, s_lo); s_lo = fmaf(u1, u1, s_lo);
                s_hi = fmaf(v0, v0, s_hi); s_hi = fmaf(v1, v1, s_hi);
            }
            s_lo += __shfl_xor_sync(0xffffffffu, s_lo, 1);
            s_lo += __shfl_xor_sync(0xffffffffu, s_lo, 2);
            s_hi += __shfl_xor_sync(0xffffffffu, s_hi, 1);
            s_hi += __shfl_xor_sync(0xffffffffu, s_hi, 2);
            if (gk == 0) {
                partF[ng * 128 + 32 * mg + 16 * mi + gr] = s_lo;
                partF[ng * 128 + 32 * mg + 16 * mi + 8 + gr] = s_hi;
            }
        }
    }
    __syncthreads();

    if (tid < MTILE)
        out[rowbase + tid] = partF[tid] + partF[128 + tid] - sqs[tid];
}

extern "C" void kernel_launch(void* const* d_in, const int* in_sizes, int n_in,
                              void* d_out, int out_size)
{
    const float* features = (const float*)d_in[0];
    const float* W        = (const float*)d_in[1];
    if (n_in >= 2 && in_sizes[0] < in_sizes[1]) {
        features = (const float*)d_in[1];
        W        = (const float*)d_in[0];
    }
    float* out = (float*)d_out;

    cudaFuncSetAttribute(fm_kernel,
                         cudaFuncAttributeMaxDynamicSharedMemorySize, SMEM_TOTAL);

    const int B = out_size;              // 16384
    const int blocks = B / MTILE;        // 128 -> 1 CTA/SM, single wave
    fm_kernel<<<blocks, THREADS, SMEM_TOTAL>>>(features, W, out);
}

// round 12
// speedup vs baseline: 1.0449x; 1.0449x over previous
#include <cuda_runtime.h>
#include <cstdint>

// FM second-order term via split-TF32 mma.sync (m16n8k8), single kernel,
// ZERO conversion passes.
//   sum_emb = features @ W  (M=16384, K=200->208, N=64)
//   x = hi+lo per operand (hi = mask13, lo = x-hi, both in registers);
//   x@W ~ Ah@Bh + Ah@Bl + Al@Bh, fp32 accum (HW truncates operands to tf32).
//   out[b] = sum_e sum_emb[b,e]^2 - sum_f features[b,f]^2 * w2sum[f]
// A raw fp32 smem (stride 212 fl), B raw fp32 smem (stride 72 fl, k-major);
// both cp.async'd. 512 thr, 16 warps = mg4 x ng4, warp m32 x n16, full K.

typedef unsigned long long ull;

constexpr int F_DIM = 200;
constexpr int E_DIM = 64;
constexpr int MTILE = 128;
constexpr int THREADS = 512;
constexpr int NS = 26;               // k8-steps (208 >= 200)

constexpr int SA_F = 212;            // A row stride (floats; 848B)
constexpr int SB_F = 72;             // B row stride (floats; 288B) 72%32=8
constexpr int SM_A    = 0;           // 128*848  = 108544
constexpr int SM_B    = 108544;      // 208*288  = 59904
constexpr int SM_W2S  = 168448;      // 200*4
constexpr int SM_SQS  = 169248;      // 128*4
constexpr int SM_PART = 169760;      // 512*4
constexpr int SMEM_TOTAL = 171808;

__device__ __forceinline__ uint32_t smem_u32(const void* p) {
    return (uint32_t)__cvta_generic_to_shared(p);
}
__device__ __forceinline__ void cp_async16(uint32_t s, const void* g) {
    asm volatile("cp.async.cg.shared.global [%0], [%1], 16;" :: "r"(s), "l"(g));
}
__device__ __forceinline__ float lds32f(uint32_t a) {
    float v; asm volatile("ld.shared.f32 %0, [%1];" : "=f"(v) : "r"(a)); return v;
}
__device__ __forceinline__ void split13(float x, uint32_t& hi, uint32_t& lo) {
    hi = __float_as_uint(x) & 0xFFFFE000u;
    lo = __float_as_uint(x - __uint_as_float(hi));
}
__device__ __forceinline__ void mma_tf32(float* c, uint32_t a0, uint32_t a1,
                                         uint32_t a2, uint32_t a3,
                                         uint32_t b0, uint32_t b1) {
    asm volatile(
        "mma.sync.aligned.m16n8k8.row.col.f32.tf32.tf32.f32 "
        "{%0,%1,%2,%3}, {%4,%5,%6,%7}, {%8,%9}, {%0,%1,%2,%3};"
        : "+f"(c[0]), "+f"(c[1]), "+f"(c[2]), "+f"(c[3])
        : "r"(a0), "r"(a1), "r"(a2), "r"(a3), "r"(b0), "r"(b1));
}

__global__ void __launch_bounds__(THREADS, 1)
fm_kernel(const float* __restrict__ features,
          const float* __restrict__ W,
          float* __restrict__ out)
{
    extern __shared__ __align__(16) char smem[];
    const uint32_t sb = smem_u32(smem);
    const int tid = threadIdx.x;
    const int w = tid >> 5, lane = tid & 31;
    const int mg = w >> 2, ng = w & 3;          // warp: rows 32mg, cols 16ng
    const int gr = lane >> 2, gk = lane & 3;

    float* w2s  = (float*)(smem + SM_W2S);
    float* sqs  = (float*)(smem + SM_SQS);
    float* part = (float*)(smem + SM_PART);

    const size_t rowbase = (size_t)blockIdx.x * MTILE;
    const float* fblk = features + rowbase * F_DIM;

    // ---- cp.async A raw fp32: 128 rows x 50 chunks of 16B
    #pragma unroll
    for (int i = 0; i < 13; ++i) {
        const int p = tid + i * THREADS;
        if (p < 6400) {
            const int row = p / 50, ch = p - row * 50;
            cp_async16(sb + SM_A + row * 848 + ch * 16,
                       fblk + row * F_DIM + ch * 4);
        }
    }
    // ---- cp.async B raw fp32: 200 rows x 16 chunks of 16B (stride 288B)
    #pragma unroll
    for (int i = 0; i < 7; ++i) {
        const int p = tid + i * THREADS;
        if (p < 3200) {
            const int row = p >> 4, ch = p & 15;
            cp_async16(sb + SM_B + row * 288 + ch * 16,
                       W + row * E_DIM + ch * 4);
        }
    }
    asm volatile("cp.async.commit_group;");

    // ---- zero pads: A cols [200,208), B rows [200,208)
    {
        const int row = tid >> 2, c0 = 200 + (tid & 3) * 2;
        *(float2*)(smem + SM_A + (row * SA_F + c0) * 4) = make_float2(0.f, 0.f);
    }
    if (tid < 144)
        *(uint4*)(smem + SM_B + 200 * 288 + tid * 16) = make_uint4(0, 0, 0, 0);

    // ---- w2sum[f] = sum_e W[f,e]^2 (global read, overlaps cp flight)
    if (tid < F_DIM) {
        const float4* wr = (const float4*)(W + (size_t)tid * E_DIM);
        float s = 0.f;
        #pragma unroll
        for (int i = 0; i < E_DIM / 4; ++i) {
            float4 v = wr[i];
            s = fmaf(v.x, v.x, s); s = fmaf(v.y, v.y, s);
            s = fmaf(v.z, v.z, s); s = fmaf(v.w, v.w, s);
        }
        w2s[tid] = s;
    }

    asm volatile("cp.async.wait_group 0;" ::: "memory");
    __syncthreads();

    // ---- MMA mainloop: warp tile m32 x n16, full K (26 k8-steps)
    const uint32_t aB = sb + SM_A + (uint32_t)(((32 * mg + gr) * SA_F + gk) * 4);
    // B lane base: row (8s + gk [+4]), col 8t + gr; t = 2ng + j
    const uint32_t bB = sb + SM_B + (uint32_t)((gk * SB_F + 16 * ng + gr) * 4);

    float c[2][2][4];
    #pragma unroll
    for (int mi = 0; mi < 2; ++mi)
        #pragma unroll
        for (int j = 0; j < 2; ++j)
            #pragma unroll
            for (int q = 0; q < 4; ++q) c[mi][j][q] = 0.f;

    #pragma unroll
    for (int s = 0; s < NS; ++s) {
        // A: 8 fp32, rows 32mg+gr+8u, cols 8s+gk+4v (conflict-free)
        float a[8];
        #pragma unroll
        for (int u = 0; u < 4; ++u)
            #pragma unroll
            for (int v = 0; v < 2; ++v)
                a[u * 2 + v] = lds32f(aB + (uint32_t)(s * 32 + v * 16 + u * 8 * SA_F * 4));
        // B: 4 fp32, rows 8s+gk (+4), cols 16ng+8j+gr (conflict-free: 8gk+gr)
        float b[2][2];
        #pragma unroll
        for (int j = 0; j < 2; ++j)
            #pragma unroll
            for (int h = 0; h < 2; ++h)
                b[j][h] = lds32f(bB + (uint32_t)((s * 8 + h * 4) * 288 + j * 32));

        // in-register tf32 splits
        uint32_t ah[8], al[8];
        #pragma unroll
        for (int q = 0; q < 8; ++q) split13(a[q], ah[q], al[q]);
        uint32_t bh[2][2], bl[2][2];
        #pragma unroll
        for (int j = 0; j < 2; ++j)
            #pragma unroll
            for (int h = 0; h < 2; ++h) split13(b[j][h], bh[j][h], bl[j][h]);

        // hh (4 indep), hl (4), lh (4)
        mma_tf32(c[0][0], ah[0], ah[2], ah[1], ah[3], bh[0][0], bh[0][1]);
        mma_tf32(c[0][1], ah[0], ah[2], ah[1], ah[3], bh[1][0], bh[1][1]);
        mma_tf32(c[1][0], ah[4], ah[6], ah[5], ah[7], bh[0][0], bh[0][1]);
        mma_tf32(c[1][1], ah[4], ah[6], ah[5], ah[7], bh[1][0], bh[1][1]);

        mma_tf32(c[0][0], ah[0], ah[2], ah[1], ah[3], bl[0][0], bl[0][1]);
        mma_tf32(c[0][1], ah[0], ah[2], ah[1], ah[3], bl[1][0], bl[1][1]);
        mma_tf32(c[1][0], ah[4], ah[6], ah[5], ah[7], bl[0][0], bl[0][1]);
        mma_tf32(c[1][1], ah[4], ah[6], ah[5], ah[7], bl[1][0], bl[1][1]);

        mma_tf32(c[0][0], al[0], al[2], al[1], al[3], bh[0][0], bh[0][1]);
        mma_tf32(c[0][1], al[0], al[2], al[1], al[3], bh[1][0], bh[1][1]);
        mma_tf32(c[1][0], al[4], al[6], al[5], al[7], bh[0][0], bh[0][1]);
        mma_tf32(c[1][1], al[4], al[6], al[5], al[7], bh[1][0], bh[1][1]);
    }

    // ---- epilogue: per-row sum of squares over this warp's 16 cols
    {
        float su[4];
        #pragma unroll
        for (int u = 0; u < 4; ++u) {
            const int mi = u >> 1, cr = (u & 1) * 2;
            su[u] = c[mi][0][cr] * c[mi][0][cr] + c[mi][0][cr + 1] * c[mi][0][cr + 1]
                  + c[mi][1][cr] * c[mi][1][cr] + c[mi][1][cr + 1] * c[mi][1][cr + 1];
        }
        #pragma unroll
        for (int u = 0; u < 4; ++u) {
            su[u] += __shfl_xor_sync(0xffffffffu, su[u], 1);
            su[u] += __shfl_xor_sync(0xffffffffu, su[u], 2);
        }
        if (gk == 0) {
            #pragma unroll
            for (int u = 0; u < 4; ++u)
                part[ng * 128 + 32 * mg + 8 * u + gr] = su[u];
        }
    }

    // ---- sq term from smem A (raw fp32)
    {
        const int row = tid >> 2, q = tid & 3;
        const uint32_t aRow = sb + SM_A + (uint32_t)(row * 848);
        float s0 = 0.f, s1 = 0.f;
        #pragma unroll
        for (int j = 0; j < 50; j += 2) {
            const int f0 = q + 4 * j, f1 = q + 4 * (j + 1);
            const float x0 = lds32f(aRow + f0 * 4);
            const float x1 = lds32f(aRow + f1 * 4);
            s0 = fmaf(x0 * x0, w2s[f0], s0);
            s1 = fmaf(x1 * x1, w2s[f1], s1);
        }
        float sq = s0 + s1;
        sq += __shfl_xor_sync(0xffffffffu, sq, 1);
        sq += __shfl_xor_sync(0xffffffffu, sq, 2);
        if (q == 0) sqs[row] = sq;
    }
    __syncthreads();

    if (tid < MTILE)
        out[rowbase + tid] = part[tid] + part[128 + tid] + part[256 + tid] +
                             part[384 + tid] - sqs[tid];
}

extern "C" void kernel_launch(void* const* d_in, const int* in_sizes, int n_in,
                              void* d_out, int out_size)
{
    const float* features = (const float*)d_in[0];
    const float* W        = (const float*)d_in[1];
    if (n_in >= 2 && in_sizes[0] < in_sizes[1]) {
        features = (const float*)d_in[1];
        W        = (const float*)d_in[0];
    }
    float* out = (float*)d_out;

    cudaFuncSetAttribute(fm_kernel,
                         cudaFuncAttributeMaxDynamicSharedMemorySize, SMEM_TOTAL);

    const int B = out_size;              // 16384
    const int blocks = B / MTILE;        // 128 -> 1 CTA/SM, single wave
    fm_kernel<<<blocks, THREADS, SMEM_TOTAL>>>(features, W, out);
}

// round 13
// speedup vs baseline: 1.0607x; 1.0152x over previous
#include <cuda_runtime.h>
#include <cstdint>

// FM second-order term via split-TF32 mma.sync (m16n8k8), single kernel.
//   sum_emb = features @ W  (M=16384, K=200->208, N=64)
//   x = hi+lo (tf32 split); x@W ~ Ah@Bh + Ah@Bl + Al@Bh, fp32 accum.
//   out[b] = sum_e sum_emb[b,e]^2 - sum_f features[b,f]^2 * w2sum[f]
// R13: R10's proven mainloop (fragment-linear B hi/lo planes, LDS.128),
// with B conversion fused in-CTA via coalesced 8x8 tile LDG + shfl.idx
// (no gather, no prep kernel), overlapped with the A cp.async flight.
// 512 thr, 16 warps = mg4 x ng4, warp tile m32 x n16, full K (26 k8-steps).

typedef unsigned long long ull;

constexpr int F_DIM = 200;
constexpr int E_DIM = 64;
constexpr int MTILE = 128;
constexpr int THREADS = 512;
constexpr int NS = 26;               // k8-steps (208 >= 200)

constexpr int SA_F = 212;            // A smem row stride (floats; 848B)
constexpr int SM_A    = 0;           // 128*848       = 108544
constexpr int SM_B    = 108544;      // 208 blk * 512 = 106496 (frag-linear)
constexpr int SM_W2S  = 215040;      // 200*4
constexpr int SM_SQS  = 215840;      // 128*4
constexpr int SM_PART = 216352;      // 512*4
constexpr int SMEM_TOTAL = 218400;

__device__ __forceinline__ uint32_t smem_u32(const void* p) {
    return (uint32_t)__cvta_generic_to_shared(p);
}
__device__ __forceinline__ void cp_async16(uint32_t s, const void* g) {
    asm volatile("cp.async.cg.shared.global [%0], [%1], 16;" :: "r"(s), "l"(g));
}
__device__ __forceinline__ float lds32f(uint32_t a) {
    float v; asm volatile("ld.shared.f32 %0, [%1];" : "=f"(v) : "r"(a)); return v;
}
__device__ __forceinline__ uint4 lds128(uint32_t a) {
    uint4 v;
    asm volatile("ld.shared.v4.b32 {%0,%1,%2,%3}, [%4];"
                 : "=r"(v.x), "=r"(v.y), "=r"(v.z), "=r"(v.w) : "r"(a));
    return v;
}
__device__ __forceinline__ void split13(float x, uint32_t& hi, uint32_t& lo) {
    hi = __float_as_uint(x) & 0xFFFFE000u;
    lo = __float_as_uint(x - __uint_as_float(hi));
}
__device__ __forceinline__ void mma_tf32(float* c, uint32_t a0, uint32_t a1,
                                         uint32_t a2, uint32_t a3,
                                         uint32_t b0, uint32_t b1) {
    asm volatile(
        "mma.sync.aligned.m16n8k8.row.col.f32.tf32.tf32.f32 "
        "{%0,%1,%2,%3}, {%4,%5,%6,%7}, {%8,%9}, {%0,%1,%2,%3};"
        : "+f"(c[0]), "+f"(c[1]), "+f"(c[2]), "+f"(c[3])
        : "r"(a0), "r"(a1), "r"(a2), "r"(a3), "r"(b0), "r"(b1));
}

__global__ void __launch_bounds__(THREADS, 1)
fm_kernel(const float* __restrict__ features,
          const float* __restrict__ W,
          float* __restrict__ out)
{
    extern __shared__ __align__(16) char smem[];
    const uint32_t sb = smem_u32(smem);
    const int tid = threadIdx.x;
    const int w = tid >> 5, lane = tid & 31;
    const int mg = w >> 2, ng = w & 3;          // warp: rows 32mg, cols 16ng
    const int gr = lane >> 2, gk = lane & 3;

    float* w2s  = (float*)(smem + SM_W2S);
    float* sqs  = (float*)(smem + SM_SQS);
    float* part = (float*)(smem + SM_PART);

    const size_t rowbase = (size_t)blockIdx.x * MTILE;
    const float* fblk = features + rowbase * F_DIM;

    // ---- 1. cp.async A raw fp32: 128 rows x 50 chunks of 16B
    #pragma unroll
    for (int i = 0; i < 13; ++i) {
        const int p = tid + i * THREADS;
        if (p < 6400) {
            const int row = p / 50, ch = p - row * 50;
            cp_async16(sb + SM_A + row * 848 + ch * 16,
                       fblk + row * F_DIM + ch * 4);
        }
    }
    asm volatile("cp.async.commit_group;");

    // ---- 2. zero A K-pad cols [200,208) (bytes disjoint from cp.async)
    {
        const int row = tid >> 2, c0 = 200 + (tid & 3) * 2;
        *(float2*)(smem + SM_A + (row * SA_F + c0) * 4) = make_float2(0.f, 0.f);
    }

    // ---- 3. B conversion (overlaps A flight): coalesced tile LDG + shfl.
    // Frag block bi = t*26+s holds 8x8 W tile (k=8s..+7, e=8t..+7); lane l
    // of the frag needs b0=W[8s+(l&3)][8t+(l>>2)], b1 at row+4. Tile loaded
    // as x0=W[8s+(l>>3)][8t+(l&7)], x1 at row+4 -> both wanted elements live
    // in the SAME source lane L0 = ((l&3)<<3)|(l>>2).
    #pragma unroll
    for (int it = 0; it < 13; ++it) {
        const int bi = (tid >> 5) + it * 16;     // 0..207
        const int t = bi / 26, s = bi - 26 * t;
        const int k0 = 8 * s + (lane >> 3);      // tile-load row (x0)
        const int e0 = 8 * t + (lane & 7);       // tile-load col
        const float x0 = (k0 < F_DIM) ? W[(size_t)k0 * E_DIM + e0] : 0.f;
        const float x1 = (k0 + 4 < F_DIM) ? W[(size_t)(k0 + 4) * E_DIM + e0] : 0.f;
        const int L0 = ((lane & 3) << 3) | (lane >> 2);
        const float b0 = __shfl_sync(0xffffffffu, x0, L0);
        const float b1 = __shfl_sync(0xffffffffu, x1, L0);
        uint32_t b0h, b0l, b1h, b1l;
        split13(b0, b0h, b0l);
        split13(b1, b1h, b1l);
        *(uint4*)(smem + SM_B + bi * 512 + lane * 16) =
            make_uint4(b0h, b1h, b0l, b1l);
    }

    // ---- 4. w2sum[f] = sum_e W[f,e]^2 (L2-hot, overlaps A flight)
    if (tid < F_DIM) {
        const float4* wr = (const float4*)(W + (size_t)tid * E_DIM);
        float s = 0.f;
        #pragma unroll
        for (int i = 0; i < E_DIM / 4; ++i) {
            float4 v = wr[i];
            s = fmaf(v.x, v.x, s); s = fmaf(v.y, v.y, s);
            s = fmaf(v.z, v.z, s); s = fmaf(v.w, v.w, s);
        }
        w2s[tid] = s;
    }

    asm volatile("cp.async.wait_group 0;" ::: "memory");
    __syncthreads();

    // ---- 5. MMA mainloop (R10 verbatim): warp m32 x n16, 26 k8-steps
    const uint32_t aB = sb + SM_A + (uint32_t)(((32 * mg + gr) * SA_F + gk) * 4);
    const uint32_t bB = sb + SM_B + (uint32_t)((2 * ng * 26) * 512 + lane * 16);

    float c[2][2][4];
    #pragma unroll
    for (int mi = 0; mi < 2; ++mi)
        #pragma unroll
        for (int j = 0; j < 2; ++j)
            #pragma unroll
            for (int q = 0; q < 4; ++q) c[mi][j][q] = 0.f;

    #pragma unroll
    for (int s = 0; s < NS; ++s) {
        // A: 8 fp32, rows 32mg+gr+8u, cols 8s+gk+4v (conflict-free banks)
        float a[8];
        #pragma unroll
        for (int u = 0; u < 4; ++u)
            #pragma unroll
            for (int v = 0; v < 2; ++v)
                a[u * 2 + v] = lds32f(aB + (uint32_t)(s * 32 + v * 16 + u * 8 * SA_F * 4));
        uint32_t ah[8], al[8];
        #pragma unroll
        for (int q = 0; q < 8; ++q) split13(a[q], ah[q], al[q]);

        // B frags: one LDS.128 per n8-tile = {b0h,b1h,b0l,b1l}
        const uint4 B0 = lds128(bB + s * 512);
        const uint4 B1 = lds128(bB + 13312 + s * 512);

        // hh (4 independent accums), then hl, then lh
        mma_tf32(c[0][0], ah[0], ah[2], ah[1], ah[3], B0.x, B0.y);
        mma_tf32(c[0][1], ah[0], ah[2], ah[1], ah[3], B1.x, B1.y);
        mma_tf32(c[1][0], ah[4], ah[6], ah[5], ah[7], B0.x, B0.y);
        mma_tf32(c[1][1], ah[4], ah[6], ah[5], ah[7], B1.x, B1.y);

        mma_tf32(c[0][0], ah[0], ah[2], ah[1], ah[3], B0.z, B0.w);
        mma_tf32(c[0][1], ah[0], ah[2], ah[1], ah[3], B1.z, B1.w);
        mma_tf32(c[1][0], ah[4], ah[6], ah[5], ah[7], B0.z, B0.w);
        mma_tf32(c[1][1], ah[4], ah[6], ah[5], ah[7], B1.z, B1.w);

        mma_tf32(c[0][0], al[0], al[2], al[1], al[3], B0.x, B0.y);
        mma_tf32(c[0][1], al[0], al[2], al[1], al[3], B1.x, B1.y);
        mma_tf32(c[1][0], al[4], al[6], al[5], al[7], B0.x, B0.y);
        mma_tf32(c[1][1], al[4], al[6], al[5], al[7], B1.x, B1.y);
    }

    // ---- 6. epilogue: per-row sum of squares over this warp's 16 cols
    {
        float su[4];
        #pragma unroll
        for (int u = 0; u < 4; ++u) {
            const int mi = u >> 1, cr = (u & 1) * 2;
            su[u] = c[mi][0][cr] * c[mi][0][cr] + c[mi][0][cr + 1] * c[mi][0][cr + 1]
                  + c[mi][1][cr] * c[mi][1][cr] + c[mi][1][cr + 1] * c[mi][1][cr + 1];
        }
        #pragma unroll
        for (int u = 0; u < 4; ++u) {
            su[u] += __shfl_xor_sync(0xffffffffu, su[u], 1);
            su[u] += __shfl_xor_sync(0xffffffffu, su[u], 2);
        }
        if (gk == 0) {
            #pragma unroll
            for (int u = 0; u < 4; ++u)
                part[ng * 128 + 32 * mg + 8 * u + gr] = su[u];
        }
    }

    // ---- 7. sq term from smem A (raw fp32, exact)
    {
        const int row = tid >> 2, q = tid & 3;
        const uint32_t aRow = sb + SM_A + (uint32_t)(row * 848);
        float s0 = 0.f, s1 = 0.f;
        #pragma unroll
        for (int j = 0; j < 50; j += 2) {
            const int f0 = q + 4 * j, f1 = q + 4 * (j + 1);
            const float x0 = lds32f(aRow + f0 * 4);
            const float x1 = lds32f(aRow + f1 * 4);
            s0 = fmaf(x0 * x0, w2s[f0], s0);
            s1 = fmaf(x1 * x1, w2s[f1], s1);
        }
        float sq = s0 + s1;
        sq += __shfl_xor_sync(0xffffffffu, sq, 1);
        sq += __shfl_xor_sync(0xffffffffu, sq, 2);
        if (q == 0) sqs[row] = sq;
    }
    __syncthreads();

    if (tid < MTILE)
        out[rowbase + tid] = part[tid] + part[128 + tid] + part[256 + tid] +
                             part[384 + tid] - sqs[tid];
}

extern "C" void kernel_launch(void* const* d_in, const int* in_sizes, int n_in,
                              void* d_out, int out_size)
{
    const float* features = (const float*)d_in[0];
    const float* W        = (const float*)d_in[1];
    if (n_in >= 2 && in_sizes[0] < in_sizes[1]) {
        features = (const float*)d_in[1];
        W        = (const float*)d_in[0];
    }
    float* out = (float*)d_out;

    cudaFuncSetAttribute(fm_kernel,
                         cudaFuncAttributeMaxDynamicSharedMemorySize, SMEM_TOTAL);

    const int B = out_size;              // 16384
    const int blocks = B / MTILE;        // 128 -> 1 CTA/SM, single wave
    fm_kernel<<<blocks, THREADS, SMEM_TOTAL>>>(features, W, out);
}

// round 14
// speedup vs baseline: 1.1843x; 1.1165x over previous
#include <cuda_runtime.h>
#include <cstdint>

// FM second-order term via split-TF32 mma.sync (m16n8k8), single kernel,
// zero conversion passes, zero pre-barrier W work.
//   sum_emb = features @ W  (M=16384, K=200->208, N=64)
//   per operand: hi = mask13(x), lo = x-hi (registers); HW truncates to tf32.
//   x@W ~ Ah@Bh + Ah@Bl + Al@Bh, fp32 accum.
//   out[b] = sum_e sum_emb[b,e]^2 - sum_f features[b,f]^2 * w2sum[f]
// R14 = R12 + register double-buffered fragments (loads of step s+1 overlap
// MMAs of step s) + w2sum moved post-mainloop, computed from Braw smem (LDS
// only). Pre-barrier = two coalesced cp.async streams, nothing else.
// 512 thr, 16 warps = mg4 x ng4, warp tile m32 x n16, full K (26 k8-steps).

typedef unsigned long long ull;

constexpr int F_DIM = 200;
constexpr int E_DIM = 64;
constexpr int MTILE = 128;
constexpr int THREADS = 512;
constexpr int NS = 26;               // k8-steps (208 >= 200)

constexpr int SA_F = 212;            // A row stride (floats; 848B)
constexpr int SB_F = 72;             // B row stride (floats; 288B) 72%32=8
constexpr int SM_A    = 0;           // 128*848  = 108544
constexpr int SM_B    = 108544;      // 208*288  = 59904
constexpr int SM_W2S  = 168448;      // 200*4
constexpr int SM_SQS  = 169248;      // 128*4
constexpr int SM_PART = 169760;      // 512*4
constexpr int SMEM_TOTAL = 171808;

__device__ __forceinline__ uint32_t smem_u32(const void* p) {
    return (uint32_t)__cvta_generic_to_shared(p);
}
__device__ __forceinline__ void cp_async16(uint32_t s, const void* g) {
    asm volatile("cp.async.cg.shared.global [%0], [%1], 16;" :: "r"(s), "l"(g));
}
__device__ __forceinline__ float lds32f(uint32_t a) {
    float v; asm volatile("ld.shared.f32 %0, [%1];" : "=f"(v) : "r"(a)); return v;
}
__device__ __forceinline__ void split13(float x, uint32_t& hi, uint32_t& lo) {
    hi = __float_as_uint(x) & 0xFFFFE000u;
    lo = __float_as_uint(x - __uint_as_float(hi));
}
__device__ __forceinline__ void mma_tf32(float* c, uint32_t a0, uint32_t a1,
                                         uint32_t a2, uint32_t a3,
                                         uint32_t b0, uint32_t b1) {
    asm volatile(
        "mma.sync.aligned.m16n8k8.row.col.f32.tf32.tf32.f32 "
        "{%0,%1,%2,%3}, {%4,%5,%6,%7}, {%8,%9}, {%0,%1,%2,%3};"
        : "+f"(c[0]), "+f"(c[1]), "+f"(c[2]), "+f"(c[3])
        : "r"(a0), "r"(a1), "r"(a2), "r"(a3), "r"(b0), "r"(b1));
}

__global__ void __launch_bounds__(THREADS, 1)
fm_kernel(const float* __restrict__ features,
          const float* __restrict__ W,
          float* __restrict__ out)
{
    extern __shared__ __align__(16) char smem[];
    const uint32_t sb = smem_u32(smem);
    const int tid = threadIdx.x;
    const int w = tid >> 5, lane = tid & 31;
    const int mg = w >> 2, ng = w & 3;          // warp: rows 32mg, cols 16ng
    const int gr = lane >> 2, gk = lane & 3;

    float* w2s  = (float*)(smem + SM_W2S);
    float* sqs  = (float*)(smem + SM_SQS);
    float* part = (float*)(smem + SM_PART);

    const size_t rowbase = (size_t)blockIdx.x * MTILE;
    const float* fblk = features + rowbase * F_DIM;

    // ---- pre-barrier: ONLY coalesced cp.async + pad zeroing ----
    // A raw fp32: 128 rows x 50 chunks of 16B
    #pragma unroll
    for (int i = 0; i < 13; ++i) {
        const int p = tid + i * THREADS;
        if (p < 6400) {
            const int row = p / 50, ch = p - row * 50;
            cp_async16(sb + SM_A + row * 848 + ch * 16,
                       fblk + row * F_DIM + ch * 4);
        }
    }
    // B raw fp32: 200 rows x 16 chunks of 16B (row stride 288B)
    #pragma unroll
    for (int i = 0; i < 7; ++i) {
        const int p = tid + i * THREADS;
        if (p < 3200) {
            const int row = p >> 4, ch = p & 15;
            cp_async16(sb + SM_B + row * 288 + ch * 16,
                       W + row * E_DIM + ch * 4);
        }
    }
    asm volatile("cp.async.commit_group;");

    // zero pads: A cols [200,208), B rows [200,208)
    {
        const int row = tid >> 2, c0 = 200 + (tid & 3) * 2;
        *(float2*)(smem + SM_A + (row * SA_F + c0) * 4) = make_float2(0.f, 0.f);
    }
    if (tid < 144)
        *(uint4*)(smem + SM_B + 200 * 288 + tid * 16) = make_uint4(0, 0, 0, 0);

    asm volatile("cp.async.wait_group 0;" ::: "memory");
    __syncthreads();

    // ---- MMA mainloop: warp m32 x n16, 26 k8-steps, double-buffered frags
    const uint32_t aB = sb + SM_A + (uint32_t)(((32 * mg + gr) * SA_F + gk) * 4);
    const uint32_t bB = sb + SM_B + (uint32_t)((gk * SB_F + 16 * ng + gr) * 4);

    float c[2][2][4];
    #pragma unroll
    for (int mi = 0; mi < 2; ++mi)
        #pragma unroll
        for (int j = 0; j < 2; ++j)
            #pragma unroll
            for (int q = 0; q < 4; ++q) c[mi][j][q] = 0.f;

    float a_c[8], b_c[4], a_n[8], b_n[4];
    // A frag: rows 32mg+gr+8u, cols 8s+gk+4v -> a[u*2+v]
    #pragma unroll
    for (int u = 0; u < 4; ++u)
        #pragma unroll
        for (int v = 0; v < 2; ++v)
            a_c[u * 2 + v] = lds32f(aB + (uint32_t)(v * 16 + u * 8 * SA_F * 4));
    // B frag: rows 8s+gk+4h, cols 16ng+8j+gr -> b[j*2+h]
    #pragma unroll
    for (int j = 0; j < 2; ++j)
        #pragma unroll
        for (int h = 0; h < 2; ++h)
            b_c[j * 2 + h] = lds32f(bB + (uint32_t)(h * 4 * 288 + j * 32));

    #pragma unroll
    for (int s = 0; s < NS; ++s) {
        // prefetch step s+1 fragments (dummy-wrap on last step)
        const int sn = (s + 1 < NS) ? s + 1 : 0;
        #pragma unroll
        for (int u = 0; u < 4; ++u)
            #pragma unroll
            for (int v = 0; v < 2; ++v)
                a_n[u * 2 + v] =
                    lds32f(aB + (uint32_t)(sn * 32 + v * 16 + u * 8 * SA_F * 4));
        #pragma unroll
        for (int j = 0; j < 2; ++j)
            #pragma unroll
            for (int h = 0; h < 2; ++h)
                b_n[j * 2 + h] =
                    lds32f(bB + (uint32_t)((sn * 8 + h * 4) * 288 + j * 32));

        // split current fragments (registers only)
        uint32_t ah[8], al[8], bh[4], bl[4];
        #pragma unroll
        for (int q = 0; q < 8; ++q) split13(a_c[q], ah[q], al[q]);
        #pragma unroll
        for (int q = 0; q < 4; ++q) split13(b_c[q], bh[q], bl[q]);

        // 12 MMAs: hh (4 indep accums), hl, lh
        mma_tf32(c[0][0], ah[0], ah[2], ah[1], ah[3], bh[0], bh[1]);
        mma_tf32(c[0][1], ah[0], ah[2], ah[1], ah[3], bh[2], bh[3]);
        mma_tf32(c[1][0], ah[4], ah[6], ah[5], ah[7], bh[0], bh[1]);
        mma_tf32(c[1][1], ah[4], ah[6], ah[5], ah[7], bh[2], bh[3]);

        mma_tf32(c[0][0], ah[0], ah[2], ah[1], ah[3], bl[0], bl[1]);
        mma_tf32(c[0][1], ah[0], ah[2], ah[1], ah[3], bl[2], bl[3]);
        mma_tf32(c[1][0], ah[4], ah[6], ah[5], ah[7], bl[0], bl[1]);
        mma_tf32(c[1][1], ah[4], ah[6], ah[5], ah[7], bl[2], bl[3]);

        mma_tf32(c[0][0], al[0], al[2], al[1], al[3], bh[0], bh[1]);
        mma_tf32(c[0][1], al[0], al[2], al[1], al[3], bh[2], bh[3]);
        mma_tf32(c[1][0], al[4], al[6], al[5], al[7], bh[0], bh[1]);
        mma_tf32(c[1][1], al[4], al[6], al[5], al[7], bh[2], bh[3]);

        #pragma unroll
        for (int q = 0; q < 8; ++q) a_c[q] = a_n[q];
        #pragma unroll
        for (int q = 0; q < 4; ++q) b_c[q] = b_n[q];
    }

    // ---- epilogue: per-row sum of squares over this warp's 16 cols
    {
        float su[4];
        #pragma unroll
        for (int u = 0; u < 4; ++u) {
            const int mi = u >> 1, cr = (u & 1) * 2;
            su[u] = c[mi][0][cr] * c[mi][0][cr] + c[mi][0][cr + 1] * c[mi][0][cr + 1]
                  + c[mi][1][cr] * c[mi][1][cr] + c[mi][1][cr + 1] * c[mi][1][cr + 1];
        }
        #pragma unroll
        for (int u = 0; u < 4; ++u) {
            su[u] += __shfl_xor_sync(0xffffffffu, su[u], 1);
            su[u] += __shfl_xor_sync(0xffffffffu, su[u], 2);
        }
        if (gk == 0) {
            #pragma unroll
            for (int u = 0; u < 4; ++u)
                part[ng * 128 + 32 * mg + 8 * u + gr] = su[u];
        }
    }

    // ---- w2sum from Braw smem (LDS only, post-mainloop)
    if (tid < F_DIM) {
        const uint32_t bRow = sb + SM_B + (uint32_t)(tid * 288);
        float s = 0.f;
        #pragma unroll
        for (int i = 0; i < 16; ++i) {
            const float4 v = *(const float4*)(smem + SM_B + tid * 288 + i * 16);
            s = fmaf(v.x, v.x, s); s = fmaf(v.y, v.y, s);
            s = fmaf(v.z, v.z, s); s = fmaf(v.w, v.w, s);
        }
        (void)bRow;
        w2s[tid] = s;
    }
    __syncthreads();

    // ---- sq term from smem A (raw fp32, exact)
    {
        const int row = tid >> 2, q = tid & 3;
        const uint32_t aRow = sb + SM_A + (uint32_t)(row * 848);
        float s0 = 0.f, s1 = 0.f;
        #pragma unroll
        for (int j = 0; j < 50; j += 2) {
            const int f0 = q + 4 * j, f1 = q + 4 * (j + 1);
            const float x0 = lds32f(aRow + f0 * 4);
            const float x1 = lds32f(aRow + f1 * 4);
            s0 = fmaf(x0 * x0, w2s[f0], s0);
            s1 = fmaf(x1 * x1, w2s[f1], s1);
        }
        float sq = s0 + s1;
        sq += __shfl_xor_sync(0xffffffffu, sq, 1);
        sq += __shfl_xor_sync(0xffffffffu, sq, 2);
        if (q == 0) sqs[row] = sq;
    }
    __syncthreads();

    if (tid < MTILE)
        out[rowbase + tid] = part[tid] + part[128 + tid] + part[256 + tid] +
                             part[384 + tid] - sqs[tid];
}

extern "C" void kernel_launch(void* const* d_in, const int* in_sizes, int n_in,
                              void* d_out, int out_size)
{
    const float* features = (const float*)d_in[0];
    const float* W        = (const float*)d_in[1];
    if (n_in >= 2 && in_sizes[0] < in_sizes[1]) {
        features = (const float*)d_in[1];
        W        = (const float*)d_in[0];
    }
    float* out = (float*)d_out;

    cudaFuncSetAttribute(fm_kernel,
                         cudaFuncAttributeMaxDynamicSharedMemorySize, SMEM_TOTAL);

    const int B = out_size;              // 16384
    const int blocks = B / MTILE;        // 128 -> 1 CTA/SM, single wave
    fm_kernel<<<blocks, THREADS, SMEM_TOTAL>>>(features, W, out);
}